// round 8
// baseline (speedup 1.0000x reference)
#include <cuda_runtime.h>
#include <cuda_fp16.h>
#include <cstdint>

// ---------------- static device scratch ----------------
__device__ float g_h[16*64*512];
__device__ float g_r[16*64*512];
__device__ float g_kbias[16*256*512];
__device__ float g_kern[201326592];        // 8192 x 24576
__device__ float g_xa[16*32*4096];
__device__ float g_xb[16*32*4096];
__device__ __half g_b16[24576*384];        // B' = [Bh|Bl] fp16

__device__ __forceinline__ float lrelu(float v){ return v>=0.f ? v : 0.2f*v; }

__device__ __forceinline__ uint32_t smem_u32(const void* p){
  uint32_t a;
  asm("{ .reg .u64 t; cvta.to.shared.u64 t, %1; cvt.u32.u64 %0, t; }":"=r"(a):"l"(p));
  return a;
}
__device__ __forceinline__ void cp16(uint32_t d, const void* s){
  asm volatile("cp.async.cg.shared.global [%0], [%1], 16;"::"r"(d),"l"(s));
}
__device__ __forceinline__ void ldmx4(uint32_t* r, uint32_t a){
  asm volatile("ldmatrix.sync.aligned.m8n8.x4.shared.b16 {%0,%1,%2,%3},[%4];"
    :"=r"(r[0]),"=r"(r[1]),"=r"(r[2]),"=r"(r[3]):"r"(a));
}
__device__ __forceinline__ void mma16816(float* c, const uint32_t* a, uint32_t b0, uint32_t b1){
  asm volatile("mma.sync.aligned.m16n8k16.row.col.f32.f16.f16.f32 "
    "{%0,%1,%2,%3},{%4,%5,%6,%7},{%8,%9},{%0,%1,%2,%3};"
    :"+f"(c[0]),"+f"(c[1]),"+f"(c[2]),"+f"(c[3])
    :"r"(a[0]),"r"(a[1]),"r"(a[2]),"r"(a[3]),"r"(b0),"r"(b1));
}

// ---------------- generic small conv1d over L=512 (32-wide tiles) ----------------
template<int CI,int KS,bool RELU>
__global__ void conv1d_small(const float* __restrict__ in,const float* __restrict__ w,
    const float* __restrict__ bias,float* __restrict__ out,int Cout){
  const int PAD=(KS-1)/2, WDT=32+KS-1;
  const int l0=blockIdx.x*32, cg=blockIdx.y, b=blockIdx.z;
  __shared__ float s[CI][WDT];
  for(int idx=threadIdx.x; idx<CI*WDT; idx+=256){
    int ci=idx/WDT, p=idx-ci*WDT, l=l0+p-PAD;
    s[ci][p]=(l>=0&&l<512)?in[(b*CI+ci)*512+l]:0.f;
  }
  __syncthreads();
  const int co=cg*64+(threadIdx.x>>2), ls=(threadIdx.x&3)*8;
  float acc[8]; float bz=bias[co];
#pragma unroll
  for(int j=0;j<8;j++)acc[j]=bz;
  const float* wr=w+(size_t)co*CI*KS;
  for(int ci=0;ci<CI;ci++){
    float xv[8+KS-1];
#pragma unroll
    for(int j=0;j<8+KS-1;j++)xv[j]=s[ci][ls+j];
#pragma unroll
    for(int k=0;k<KS;k++){
      float wv=__ldg(&wr[ci*KS+k]);
#pragma unroll
      for(int j=0;j<8;j++)acc[j]=fmaf(wv,xv[j+k],acc[j]);
    }
  }
  float* orow=out+((size_t)b*Cout+co)*512+l0+ls;
#pragma unroll
  for(int j=0;j<8;j++){
    float v=acc[j];
    if(RELU)v=lrelu(v);
    orow[j]=v;
  }
}

// ---------------- fused residual block (FIXED boundary semantics) ----------------
// out = in + lrelu(conv2(zeropad(lrelu(conv1(in)))))
__global__ void res_fused(const float* __restrict__ in,const float* __restrict__ w1,
    const float* __restrict__ b1,const float* __restrict__ w2,const float* __restrict__ b2,
    float* __restrict__ out){
  const int l0=blockIdx.x*32, b=blockIdx.z, tid=threadIdx.x;
  __shared__ float si[64][40];   // si[p] = in[l0+p-2]
  __shared__ float r1[64][36];   // r1[p] = conv1 out at l0+p-1 (0 if out of range)
  for(int idx=tid; idx<64*40; idx+=256){
    int ci=idx/40, p=idx-ci*40, l=l0+p-2;
    si[ci][p]=(l>=0&&l<512)?in[(b*64+ci)*512+l]:0.f;
  }
  __syncthreads();
  {
    const int co=tid>>2, q=tid&3, n=(q==3)?7:9, i0=q*9;
    float acc[9]; float bz=b1[co];
#pragma unroll
    for(int j=0;j<9;j++)acc[j]=bz;
    const float* wr=w1+co*192;
    for(int ci=0;ci<64;ci++){
      float w0=__ldg(&wr[ci*3]),wA=__ldg(&wr[ci*3+1]),wB=__ldg(&wr[ci*3+2]);
#pragma unroll
      for(int j=0;j<9;j++)
        acc[j]+=w0*si[ci][i0+j]+wA*si[ci][i0+j+1]+wB*si[ci][i0+j+2];
    }
    for(int j=0;j<n;j++){
      int gl=l0+i0+j-1;                      // global conv1 position
      r1[co][i0+j]=(gl>=0&&gl<512)?lrelu(acc[j]):0.f;   // conv2 zero-pads conv1 OUTPUT
    }
  }
  __syncthreads();
  {
    const int co=tid>>2, q=tid&3, i0=q*8;
    float acc[8]; float bz=b2[co];
#pragma unroll
    for(int j=0;j<8;j++)acc[j]=bz;
    const float* wr=w2+co*192;
    for(int ci=0;ci<64;ci++){
      float w0=__ldg(&wr[ci*3]),wA=__ldg(&wr[ci*3+1]),wB=__ldg(&wr[ci*3+2]);
#pragma unroll
      for(int j=0;j<8;j++)
        acc[j]+=w0*r1[ci][i0+j]+wA*r1[ci][i0+j+1]+wB*r1[ci][i0+j+2];
    }
    const float* irow=&in[(b*64+co)*512+l0+i0];
    float* orow=&out[(b*64+co)*512+l0+i0];
    for(int j=0;j<8;j++) orow[j]=irow[j]+lrelu(acc[j]);
  }
}

// ---------------- build B' (ker_w -> fp16 hi/lo, width 384) ----------------
__global__ void build_b16_k(const float* __restrict__ kw){
  int idx=blockIdx.x*256+threadIdx.x;           // 24576*384
  int n=idx/384, kp=idx-n*384;
  int part=(kp>=192), kk=kp-(part?192:0);
  float v=kw[(size_t)n*192+kk];
  __half hi=__float2half_rn(v);
  g_b16[idx]=part?__float2half_rn(v-__half2float(hi)):hi;
}

// ---------------- mma.sync GEMM, fp16 3-pass, fused im2col A -----------------------
// kern = A(8192x192) @ B^T + ker_b; passes: Ah*Bh, Ah*Bl, Al*Bh (residual Al*Bl ~2^-22)
// smem: A 6x16KB @0 (bufs 0-2 Ah, 3-5 Al), B 2x32KB @98304.
#define BSTG 32768
#define SM_B 98304
#define SMEM_GEMM 163840
__global__ void __launch_bounds__(256,1) gemm_mma(const float* __restrict__ kerb){
  extern __shared__ __align__(128) char smem[];
  const uint32_t sb=smem_u32(smem);
  const int tid=threadIdx.x, lane=tid&31, wid=tid>>5;
  const int wm=wid&1, wn=wid>>1;
  const int m0=blockIdx.y*128, n0=blockIdx.x*256;
  const int b=m0>>9, l0=m0&511;
  const int bcol[9]={0,64,128,192,256,320,0,64,128};

  float acc[4][8][4];
#pragma unroll
  for(int i=0;i<4;i++)
#pragma unroll
    for(int j=0;j<8;j++)
#pragma unroll
      for(int k=0;k<4;k++)acc[i][j][k]=0.f;

  auto loadB=[&](int col,int st){
    uint32_t bbase=sb+SM_B+st*BSTG;
#pragma unroll
    for(int i=0;i<8;i++){
      int q=tid+i*256, row=q>>3, c=q&7;
      cp16(bbase+row*128+((c^(row&7))<<4),
           g_b16+(size_t)(n0+row)*384+col+c*8);
    }
    asm volatile("cp.async.commit_group;");
  };
  loadB(0,0);

  // fused im2col A build: bufs 0-2 hi, 3-5 lo (one g_r read each)
#pragma unroll
  for(int buf=0;buf<3;buf++){
#pragma unroll
    for(int i=0;i<16;i++){
      int idx=tid+i*256;            // 4096 = 128 rows x 32 half2
      int row=idx>>5, kkp=idx&31;
      int kk=buf*64+kkp*2;
      int l=l0+row;
      int hid0=kk/3, t0=kk-3*hid0, lp0=l+t0-1;
      float v0=(lp0>=0&&lp0<512)?g_r[(b*64+hid0)*512+lp0]:0.f;
      int kk1=kk+1, hid1=kk1/3, t1=kk1-3*hid1, lp1=l+t1-1;
      float v1=(lp1>=0&&lp1<512)?g_r[(b*64+hid1)*512+lp1]:0.f;
      __half h0=__float2half_rn(v0), h1=__float2half_rn(v1);
      __half e0=__float2half_rn(v0-__half2float(h0));
      __half e1=__float2half_rn(v1-__half2float(h1));
      __half2 hv=__halves2half2(h0,h1);
      __half2 lv=__halves2half2(e0,e1);
      int boff=kkp*4, c=boff>>4, w=boff&15;
      uint32_t dst=row*128+((c^(row&7))<<4)+w;
      *(uint32_t*)(smem+buf*16384+dst)=*(uint32_t*)&hv;
      *(uint32_t*)(smem+(buf+3)*16384+dst)=*(uint32_t*)&lv;
    }
  }

  const int l7=lane&7;
  const int rAoff=l7+((lane>>3)&1)*8, cselA=lane>>4;
  const int rBoff=l7+((lane>>4)&1)*8, cselB=(lane>>3)&1;

  for(int kc=0;kc<9;kc++){
    if(kc<8){ loadB(bcol[kc+1],(kc+1)&1); asm volatile("cp.async.wait_group 1;"); }
    else    { asm volatile("cp.async.wait_group 0;"); }
    __syncthreads();
    const int abuf=(kc<3)?kc:((kc<6)?(kc-3):(kc-3));  // 0-2:Ah 3-5:Ah 6-8:Al
    uint32_t abase=sb+abuf*16384;
    uint32_t bbase=sb+SM_B+(kc&1)*BSTG;
#pragma unroll
    for(int ks=0;ks<4;ks++){
      const int c0=ks*2;
      uint32_t ar[4][4], br[4][4];
#pragma unroll
      for(int mi=0;mi<4;mi++){
        int row=wm*64+mi*16+rAoff, cc=c0+cselA;
        ldmx4(ar[mi], abase+row*128+((cc^(row&7))<<4));
      }
#pragma unroll
      for(int np=0;np<4;np++){
        int row=wn*64+np*16+rBoff, cc=c0+cselB;
        ldmx4(br[np], bbase+row*128+((cc^(row&7))<<4));
      }
#pragma unroll
      for(int mi=0;mi<4;mi++)
#pragma unroll
        for(int ni=0;ni<8;ni++)
          mma16816(acc[mi][ni], ar[mi], br[ni>>1][(ni&1)*2], br[ni>>1][(ni&1)*2+1]);
    }
    __syncthreads();
  }

  // epilogue: + ker_b -> g_kern
  const int g=lane>>2, t2=(lane&3)*2;
#pragma unroll
  for(int mi=0;mi<4;mi++){
    const int r0=m0+wm*64+mi*16+g;
    float* row0=g_kern+(size_t)r0*24576;
    float* row1=row0+(size_t)8*24576;
#pragma unroll
    for(int ni=0;ni<8;ni++){
      int col=n0+wn*64+ni*8+t2;
      float2 bb=*(const float2*)(kerb+col);
      float2 v0,v1;
      v0.x=acc[mi][ni][0]+bb.x; v0.y=acc[mi][ni][1]+bb.y;
      v1.x=acc[mi][ni][2]+bb.x; v1.y=acc[mi][ni][3]+bb.y;
      *(float2*)(row0+col)=v0;
      *(float2*)(row1+col)=v1;
    }
  }
}

// ---------------- convt_pre: lrelu(x) -> ConvTranspose1d(k=16, s=8, p=4) --------
__global__ void convt_pre_k(const float* __restrict__ x,const float* __restrict__ ctw,
    const float* __restrict__ ctb,float* __restrict__ xx){
  const int b=blockIdx.z, cg=blockIdx.y, t0=blockIdx.x*64, tid=threadIdx.x;
  __shared__ float swt[2048];
  __shared__ float sx[32][12];
  for(int idx=tid;idx<2048;idx+=256){
    int co_l=idx>>9, ci=(idx>>4)&31, kk=idx&15;
    swt[idx]=ctw[(ci*32+cg*4+co_l)*16+kk];
  }
  const int sbase=(t0>>3)-2;
  for(int idx=tid;idx<384;idx+=256){
    int ci=idx/12, j=idx-ci*12, sp=sbase+j;
    sx[ci][j]=(sp>=0&&sp<512)?lrelu(x[(b*32+ci)*512+sp]):0.f;
  }
  __syncthreads();
  const int co_l=tid>>6, t=t0+(tid&63), co=cg*4+co_l;
  const int k0=(8+(11-t)%8)&7;
  const int j=((t+k0-11)>>3)-sbase;
  float acc=ctb[co];
  const float* wl=&swt[co_l*512];
#pragma unroll 8
  for(int ci=0;ci<32;ci++)
    acc+=sx[ci][j]*wl[ci*16+15-k0]+sx[ci][j+1]*wl[ci*16+7-k0];
  xx[(b*32+co)*4096+t]=acc;
}

// ---------------- fused LVC layer: conv block + einsum + gate, src -> dst ----------
__global__ void lvc_fused(const float* __restrict__ src,float* __restrict__ dst,
    const float* __restrict__ cbw,const float* __restrict__ cbb,
    const float* __restrict__ kbias,int layer,int dil){
  const int l=blockIdx.x, b=blockIdx.y, tid=threadIdx.x;
  __shared__ __align__(16) float sk[6144];
  __shared__ float slx[32][66];    // lrelu(src) window, zero-padded
  __shared__ float scb[32][10];    // conv block outputs at t=l*8-1..l*8+8 (0 outside)
  __shared__ float so[64][8];
  const float4* kp=(const float4*)(g_kern+((size_t)(b*512+l))*24576+layer*6144);
#pragma unroll
  for(int i=0;i<6;i++) ((float4*)sk)[tid+i*256]=kp[tid+i*256];
  const int W=10+2*dil, tb=l*8-1-dil;
  for(int idx=tid;idx<32*W;idx+=256){
    int ci=idx/W, j=idx-ci*W, t=tb+j;
    float v=(t>=0&&t<4096)?src[(b*32+ci)*4096+t]:0.f;
    slx[ci][j]=lrelu(v);
  }
  __syncthreads();
  // conv block: 320 outputs (oc, p), p -> t=l*8-1+p
  for(int idx=tid;idx<320;idx+=256){
    int oc=idx/10, p=idx-oc*10;
    int t=l*8-1+p;
    float a=cbb[oc];
    const float* wr=cbw+oc*96;
#pragma unroll 8
    for(int ic=0;ic<32;ic++){
      float w0=__ldg(&wr[ic*3]),w1=__ldg(&wr[ic*3+1]),w2=__ldg(&wr[ic*3+2]);
      a+=w0*slx[ic][p]+w1*slx[ic][p+dil]+w2*slx[ic][p+2*dil];
    }
    scb[oc][p]=(t>=0&&t<4096)?lrelu(a):0.f;
  }
  __syncthreads();
  // einsum
  const int o=tid>>2, h2=(tid&3)*2;
  float a0=0.f,a1=0.f;
#pragma unroll 4
  for(int ci=0;ci<32;ci++){
    const float* kb=&sk[ci*192+o*3];
    const float* xr=&scb[ci][h2];
    a0+=xr[0]*kb[0]+xr[1]*kb[1]+xr[2]*kb[2];
    a1+=xr[1]*kb[0]+xr[2]*kb[1]+xr[3]*kb[2];
  }
  const float bb=kbias[((b*4+layer)*64+o)*512+l];
  so[o][h2]=a0+bb; so[o][h2+1]=a1+bb;
  __syncthreads();
  // gate + residual: dst = src + sigmoid*tanh
  const int co=tid>>3, h=tid&7;
  float g=1.f/(1.f+__expf(-so[co][h]));
  float th=tanhf(so[co+32][h]);
  const size_t off=(size_t)(b*32+co)*4096+l*8+h;
  dst[off]=src[off]+g*th;
}

extern "C" void kernel_launch(void* const* d_in,const int* in_sizes,int n_in,
                              void* d_out,int out_size){
  const float* x     =(const float*)d_in[0];
  const float* c     =(const float*)d_in[1];
  const float* in_w  =(const float*)d_in[2];
  const float* in_b  =(const float*)d_in[3];
  const float* res_ws=(const float*)d_in[4];
  const float* res_bs=(const float*)d_in[5];
  const float* ker_w =(const float*)d_in[6];
  const float* ker_b =(const float*)d_in[7];
  const float* bias_w=(const float*)d_in[8];
  const float* bias_b=(const float*)d_in[9];
  const float* ct_w  =(const float*)d_in[10];
  const float* ct_b  =(const float*)d_in[11];
  const float* cb_ws =(const float*)d_in[12];
  const float* cb_bs =(const float*)d_in[13];
  float* xx=(float*)d_out;
  float *ph,*pr,*pkb,*pxa,*pxb;
  cudaGetSymbolAddress((void**)&ph, g_h);
  cudaGetSymbolAddress((void**)&pr, g_r);
  cudaGetSymbolAddress((void**)&pkb,g_kbias);
  cudaGetSymbolAddress((void**)&pxa,g_xa);
  cudaGetSymbolAddress((void**)&pxb,g_xb);

  cudaFuncSetAttribute(gemm_mma, cudaFuncAttributeMaxDynamicSharedMemorySize, SMEM_GEMM);

  build_b16_k<<<36864,256>>>(ker_w);                                          // 1
  conv1d_small<100,5,true><<<dim3(16,1,16),256>>>(c,in_w,in_b,ph,64);         // 2
  res_fused<<<dim3(16,1,16),256>>>(ph,res_ws,res_bs,res_ws+12288,res_bs+64,pr);           // 3
  res_fused<<<dim3(16,1,16),256>>>(pr,res_ws+24576,res_bs+128,res_ws+36864,res_bs+192,ph);// 4
  res_fused<<<dim3(16,1,16),256>>>(ph,res_ws+49152,res_bs+256,res_ws+61440,res_bs+320,pr);// 5
  gemm_mma<<<dim3(96,64),256,SMEM_GEMM>>>(ker_b);                             // 6 <-- profiled
  conv1d_small<64,3,false><<<dim3(16,4,16),256>>>(pr,bias_w,bias_b,pkb,256);  // 7
  convt_pre_k<<<dim3(64,8,16),256>>>(x,ct_w,ct_b,pxa);                        // 8
  const int dils[4]={1,3,9,27};
  const float* srcs[4]={pxa,pxb,pxa,pxb};
  float* dsts[4]={pxb,pxa,pxb,xx};
  for(int i=0;i<4;i++)
    lvc_fused<<<dim3(512,16),256>>>(srcs[i],dsts[i],
        cb_ws+(size_t)i*3072,cb_bs+(size_t)i*32,pkb,i,dils[i]);
}

// round 9
// speedup vs baseline: 1.1341x; 1.1341x over previous
#include <cuda_runtime.h>
#include <cuda_fp16.h>
#include <cstdint>

// ---------------- static device scratch ----------------
__device__ float g_h[16*64*512];
__device__ float g_r[16*64*512];
__device__ float g_kbias[16*256*512];
__device__ float g_kern[201326592];        // 8192 x 24576
__device__ float g_xa[16*32*4096];
__device__ float g_xb[16*32*4096];
__device__ __half g_a16[8192*192];         // A = fp16(im2col(h))
__device__ __half g_b16[24576*384];        // B' = [Bh|Bl] fp16

__device__ __forceinline__ float lrelu(float v){ return v>=0.f ? v : 0.2f*v; }

__device__ __forceinline__ uint32_t smem_u32(const void* p){
  uint32_t a;
  asm("{ .reg .u64 t; cvta.to.shared.u64 t, %1; cvt.u32.u64 %0, t; }":"=r"(a):"l"(p));
  return a;
}
__device__ __forceinline__ void cp16(uint32_t d, const void* s){
  asm volatile("cp.async.cg.shared.global [%0], [%1], 16;"::"r"(d),"l"(s));
}
__device__ __forceinline__ void ldmx4(uint32_t* r, uint32_t a){
  asm volatile("ldmatrix.sync.aligned.m8n8.x4.shared.b16 {%0,%1,%2,%3},[%4];"
    :"=r"(r[0]),"=r"(r[1]),"=r"(r[2]),"=r"(r[3]):"r"(a));
}
__device__ __forceinline__ void mma16816(float* c, const uint32_t* a, uint32_t b0, uint32_t b1){
  asm volatile("mma.sync.aligned.m16n8k16.row.col.f32.f16.f16.f32 "
    "{%0,%1,%2,%3},{%4,%5,%6,%7},{%8,%9},{%0,%1,%2,%3};"
    :"+f"(c[0]),"+f"(c[1]),"+f"(c[2]),"+f"(c[3])
    :"r"(a[0]),"r"(a[1]),"r"(a[2]),"r"(a[3]),"r"(b0),"r"(b1));
}

// ---------------- generic small conv1d over L=512 (32-wide tiles) ----------------
template<int CI,int KS,bool RELU>
__global__ void conv1d_small(const float* __restrict__ in,const float* __restrict__ w,
    const float* __restrict__ bias,float* __restrict__ out,int Cout){
  const int PAD=(KS-1)/2, WDT=32+KS-1;
  const int l0=blockIdx.x*32, cg=blockIdx.y, b=blockIdx.z;
  __shared__ float s[CI][WDT];
  for(int idx=threadIdx.x; idx<CI*WDT; idx+=256){
    int ci=idx/WDT, p=idx-ci*WDT, l=l0+p-PAD;
    s[ci][p]=(l>=0&&l<512)?in[(b*CI+ci)*512+l]:0.f;
  }
  __syncthreads();
  const int co=cg*64+(threadIdx.x>>2), ls=(threadIdx.x&3)*8;
  float acc[8]; float bz=bias[co];
#pragma unroll
  for(int j=0;j<8;j++)acc[j]=bz;
  const float* wr=w+(size_t)co*CI*KS;
  for(int ci=0;ci<CI;ci++){
    float xv[8+KS-1];
#pragma unroll
    for(int j=0;j<8+KS-1;j++)xv[j]=s[ci][ls+j];
#pragma unroll
    for(int k=0;k<KS;k++){
      float wv=__ldg(&wr[ci*KS+k]);
#pragma unroll
      for(int j=0;j<8;j++)acc[j]=fmaf(wv,xv[j+k],acc[j]);
    }
  }
  float* orow=out+((size_t)b*Cout+co)*512+l0+ls;
#pragma unroll
  for(int j=0;j<8;j++){
    float v=acc[j];
    if(RELU)v=lrelu(v);
    orow[j]=v;
  }
}

// ---------------- fused residual block (fixed boundary semantics) ----------------
__global__ void res_fused(const float* __restrict__ in,const float* __restrict__ w1,
    const float* __restrict__ b1,const float* __restrict__ w2,const float* __restrict__ b2,
    float* __restrict__ out){
  const int l0=blockIdx.x*32, b=blockIdx.z, tid=threadIdx.x;
  __shared__ float si[64][40];
  __shared__ float r1[64][36];
  for(int idx=tid; idx<64*40; idx+=256){
    int ci=idx/40, p=idx-ci*40, l=l0+p-2;
    si[ci][p]=(l>=0&&l<512)?in[(b*64+ci)*512+l]:0.f;
  }
  __syncthreads();
  {
    const int co=tid>>2, q=tid&3, n=(q==3)?7:9, i0=q*9;
    float acc[9]; float bz=b1[co];
#pragma unroll
    for(int j=0;j<9;j++)acc[j]=bz;
    const float* wr=w1+co*192;
    for(int ci=0;ci<64;ci++){
      float w0=__ldg(&wr[ci*3]),wA=__ldg(&wr[ci*3+1]),wB=__ldg(&wr[ci*3+2]);
#pragma unroll
      for(int j=0;j<9;j++)
        acc[j]+=w0*si[ci][i0+j]+wA*si[ci][i0+j+1]+wB*si[ci][i0+j+2];
    }
    for(int j=0;j<n;j++){
      int gl=l0+i0+j-1;
      r1[co][i0+j]=(gl>=0&&gl<512)?lrelu(acc[j]):0.f;   // conv2 zero-pads conv1 OUTPUT
    }
  }
  __syncthreads();
  {
    const int co=tid>>2, q=tid&3, i0=q*8;
    float acc[8]; float bz=b2[co];
#pragma unroll
    for(int j=0;j<8;j++)acc[j]=bz;
    const float* wr=w2+co*192;
    for(int ci=0;ci<64;ci++){
      float w0=__ldg(&wr[ci*3]),wA=__ldg(&wr[ci*3+1]),wB=__ldg(&wr[ci*3+2]);
#pragma unroll
      for(int j=0;j<8;j++)
        acc[j]+=w0*r1[ci][i0+j]+wA*r1[ci][i0+j+1]+wB*r1[ci][i0+j+2];
    }
    const float* irow=&in[(b*64+co)*512+l0+i0];
    float* orow=&out[(b*64+co)*512+l0+i0];
    for(int j=0;j<8;j++) orow[j]=irow[j]+lrelu(acc[j]);
  }
}

// ---------------- combined A + B' build (one launch) ----------------
// blocks [0,6144): A = fp16(im2col(g_r));  blocks [6144,43008): B' = [Bh|Bl](ker_w)
__global__ void build_ab_k(const float* __restrict__ kw){
  if(blockIdx.x<6144){
    int idx=blockIdx.x*256+threadIdx.x;         // 8192*192
    int m=idx/192, kk=idx-m*192;
    int b=m>>9, l=m&511, hid=kk/3, t=kk-hid*3;
    int lp=l+t-1;
    float v=(lp>=0&&lp<512)?g_r[(b*64+hid)*512+lp]:0.f;
    g_a16[idx]=__float2half_rn(v);
  }else{
    int idx=(blockIdx.x-6144)*256+threadIdx.x;  // 24576*384
    int n=idx/384, kp=idx-n*384;
    int part=(kp>=192), kk=kp-(part?192:0);
    float v=kw[(size_t)n*192+kk];
    __half hi=__float2half_rn(v);
    g_b16[idx]=part?__float2half_rn(v-__half2float(hi)):hi;
  }
}

// ---------------- mma.sync GEMM, fp16 2-pass: Ah*Bh + Ah*Bl (R7-proven) -----------
// CTA 128m x 256n, 8 warps (2m x 4n), warp 64x64; 6 chunks of 64; 2 stages (96KB).
#define ST_SZ 49152
__global__ void __launch_bounds__(256,1) gemm_mma(const float* __restrict__ kerb,int n_off){
  extern __shared__ __align__(128) char smem[];
  const uint32_t sb=smem_u32(smem);
  const int tid=threadIdx.x, lane=tid&31, wid=tid>>5;
  const int wm=wid&1, wn=wid>>1;
  const int m0=blockIdx.y*128, n0=(n_off+blockIdx.x)*256;

  float acc[4][8][4];
#pragma unroll
  for(int i=0;i<4;i++)
#pragma unroll
    for(int j=0;j<8;j++)
#pragma unroll
      for(int k=0;k<4;k++)acc[i][j][k]=0.f;

  auto load_stage=[&](int kc,int st){
    uint32_t abase=sb+st*ST_SZ, bbase=abase+16384;
    const int acol=(kc%3)*64;
#pragma unroll
    for(int i=0;i<4;i++){
      int q=tid+i*256, row=q>>3, c=q&7;
      cp16(abase+row*128+(((c^(row&7)))<<4),
           g_a16+(size_t)(m0+row)*192+acol+c*8);
    }
#pragma unroll
    for(int i=0;i<8;i++){
      int q=tid+i*256, row=q>>3, c=q&7;
      cp16(bbase+row*128+(((c^(row&7)))<<4),
           g_b16+(size_t)(n0+row)*384+kc*64+c*8);
    }
    asm volatile("cp.async.commit_group;");
  };

  load_stage(0,0);
  const int l7=lane&7;
  const int rAoff=l7+((lane>>3)&1)*8, cselA=lane>>4;
  const int rBoff=l7+((lane>>4)&1)*8, cselB=(lane>>3)&1;

  for(int kc=0;kc<6;kc++){
    if(kc<5) load_stage(kc+1,(kc+1)&1);
    if(kc<5) asm volatile("cp.async.wait_group 1;");
    else     asm volatile("cp.async.wait_group 0;");
    __syncthreads();
    uint32_t abase=sb+(kc&1)*ST_SZ, bbase=abase+16384;
#pragma unroll
    for(int ks=0;ks<4;ks++){
      const int c0=ks*2;
      uint32_t ar[4][4], br[4][4];
#pragma unroll
      for(int mi=0;mi<4;mi++){
        int row=wm*64+mi*16+rAoff;
        int cc=c0+cselA;
        ldmx4(ar[mi], abase+row*128+((cc^(row&7))<<4));
      }
#pragma unroll
      for(int np=0;np<4;np++){
        int row=wn*64+np*16+rBoff;
        int cc=c0+cselB;
        ldmx4(br[np], bbase+row*128+((cc^(row&7))<<4));
      }
#pragma unroll
      for(int mi=0;mi<4;mi++)
#pragma unroll
        for(int ni=0;ni<8;ni++)
          mma16816(acc[mi][ni], ar[mi], br[ni>>1][(ni&1)*2], br[ni>>1][(ni&1)*2+1]);
    }
    __syncthreads();
  }

  const int g=lane>>2, t2=(lane&3)*2;
#pragma unroll
  for(int mi=0;mi<4;mi++){
    const int r0=m0+wm*64+mi*16+g;
    float* row0=g_kern+(size_t)r0*24576;
    float* row1=row0+(size_t)8*24576;
#pragma unroll
    for(int ni=0;ni<8;ni++){
      int col=n0+wn*64+ni*8+t2;
      float2 bb=*(const float2*)(kerb+col);
      float2 v0,v1;
      v0.x=acc[mi][ni][0]+bb.x; v0.y=acc[mi][ni][1]+bb.y;
      v1.x=acc[mi][ni][2]+bb.x; v1.y=acc[mi][ni][3]+bb.y;
      *(float2*)(row0+col)=v0;
      *(float2*)(row1+col)=v1;
    }
  }
}

// ---------------- convt_pre: lrelu(x) -> ConvTranspose1d(k=16, s=8, p=4) --------
__global__ void convt_pre_k(const float* __restrict__ x,const float* __restrict__ ctw,
    const float* __restrict__ ctb,float* __restrict__ xx){
  const int b=blockIdx.z, cg=blockIdx.y, t0=blockIdx.x*64, tid=threadIdx.x;
  __shared__ float swt[2048];
  __shared__ float sx[32][12];
  for(int idx=tid;idx<2048;idx+=256){
    int co_l=idx>>9, ci=(idx>>4)&31, kk=idx&15;
    swt[idx]=ctw[(ci*32+cg*4+co_l)*16+kk];
  }
  const int sbase=(t0>>3)-2;
  for(int idx=tid;idx<384;idx+=256){
    int ci=idx/12, j=idx-ci*12, sp=sbase+j;
    sx[ci][j]=(sp>=0&&sp<512)?lrelu(x[(b*32+ci)*512+sp]):0.f;
  }
  __syncthreads();
  const int co_l=tid>>6, t=t0+(tid&63), co=cg*4+co_l;
  const int k0=(8+(11-t)%8)&7;
  const int j=((t+k0-11)>>3)-sbase;
  float acc=ctb[co];
  const float* wl=&swt[co_l*512];
#pragma unroll 8
  for(int ci=0;ci<32;ci++)
    acc+=sx[ci][j]*wl[ci*16+15-k0]+sx[ci][j+1]*wl[ci*16+7-k0];
  xx[(b*32+co)*4096+t]=acc;
}

// ---------------- fused LVC layer: conv block + einsum + gate, src -> dst ----------
__global__ void lvc_fused(const float* __restrict__ src,float* __restrict__ dst,
    const float* __restrict__ cbw,const float* __restrict__ cbb,
    const float* __restrict__ kbias,int layer,int dil){
  const int l=blockIdx.x, b=blockIdx.y, tid=threadIdx.x;
  __shared__ __align__(16) float sk[6144];
  __shared__ float slx[32][66];
  __shared__ float scb[32][10];
  __shared__ float so[64][8];
  const float4* kp=(const float4*)(g_kern+((size_t)(b*512+l))*24576+layer*6144);
#pragma unroll
  for(int i=0;i<6;i++) ((float4*)sk)[tid+i*256]=__ldcs(&kp[tid+i*256]);
  const int W=10+2*dil, tb=l*8-1-dil;
  for(int idx=tid;idx<32*W;idx+=256){
    int ci=idx/W, j=idx-ci*W, t=tb+j;
    float v=(t>=0&&t<4096)?src[(b*32+ci)*4096+t]:0.f;
    slx[ci][j]=lrelu(v);
  }
  __syncthreads();
  for(int idx=tid;idx<320;idx+=256){
    int oc=idx/10, p=idx-oc*10;
    int t=l*8-1+p;
    float a=cbb[oc];
    const float* wr=cbw+oc*96;
#pragma unroll 8
    for(int ic=0;ic<32;ic++){
      float w0=__ldg(&wr[ic*3]),w1=__ldg(&wr[ic*3+1]),w2=__ldg(&wr[ic*3+2]);
      a+=w0*slx[ic][p]+w1*slx[ic][p+dil]+w2*slx[ic][p+2*dil];
    }
    scb[oc][p]=(t>=0&&t<4096)?lrelu(a):0.f;
  }
  __syncthreads();
  const int o=tid>>2, h2=(tid&3)*2;
  float a0=0.f,a1=0.f;
#pragma unroll 4
  for(int ci=0;ci<32;ci++){
    const float* kb=&sk[ci*192+o*3];
    const float* xr=&scb[ci][h2];
    a0+=xr[0]*kb[0]+xr[1]*kb[1]+xr[2]*kb[2];
    a1+=xr[1]*kb[0]+xr[2]*kb[1]+xr[3]*kb[2];
  }
  const float bb=kbias[((b*4+layer)*64+o)*512+l];
  so[o][h2]=a0+bb; so[o][h2+1]=a1+bb;
  __syncthreads();
  const int co=tid>>3, h=tid&7;
  float g=1.f/(1.f+__expf(-so[co][h]));
  float th=tanhf(so[co+32][h]);
  const size_t off=(size_t)(b*32+co)*4096+l*8+h;
  dst[off]=src[off]+g*th;
}

extern "C" void kernel_launch(void* const* d_in,const int* in_sizes,int n_in,
                              void* d_out,int out_size){
  const float* x     =(const float*)d_in[0];
  const float* c     =(const float*)d_in[1];
  const float* in_w  =(const float*)d_in[2];
  const float* in_b  =(const float*)d_in[3];
  const float* res_ws=(const float*)d_in[4];
  const float* res_bs=(const float*)d_in[5];
  const float* ker_w =(const float*)d_in[6];
  const float* ker_b =(const float*)d_in[7];
  const float* bias_w=(const float*)d_in[8];
  const float* bias_b=(const float*)d_in[9];
  const float* ct_w  =(const float*)d_in[10];
  const float* ct_b  =(const float*)d_in[11];
  const float* cb_ws =(const float*)d_in[12];
  const float* cb_bs =(const float*)d_in[13];
  float* xx=(float*)d_out;
  float *ph,*pr,*pkb,*pxa,*pxb;
  cudaGetSymbolAddress((void**)&ph, g_h);
  cudaGetSymbolAddress((void**)&pr, g_r);
  cudaGetSymbolAddress((void**)&pkb,g_kbias);
  cudaGetSymbolAddress((void**)&pxa,g_xa);
  cudaGetSymbolAddress((void**)&pxb,g_xb);

  cudaFuncSetAttribute(gemm_mma, cudaFuncAttributeMaxDynamicSharedMemorySize, 2*ST_SZ);

  conv1d_small<100,5,true><<<dim3(16,1,16),256>>>(c,in_w,in_b,ph,64);          // 1
  res_fused<<<dim3(16,1,16),256>>>(ph,res_ws,res_bs,res_ws+12288,res_bs+64,pr);            // 2
  res_fused<<<dim3(16,1,16),256>>>(pr,res_ws+24576,res_bs+128,res_ws+36864,res_bs+192,ph); // 3
  res_fused<<<dim3(16,1,16),256>>>(ph,res_ws+49152,res_bs+256,res_ws+61440,res_bs+320,pr); // 4
  build_ab_k<<<43008,256>>>(ker_w);                                            // 5
  gemm_mma<<<dim3(32,64),256,2*ST_SZ>>>(ker_b,0);                              // 6 <-- profiled
  gemm_mma<<<dim3(32,64),256,2*ST_SZ>>>(ker_b,32);                             // 7
  gemm_mma<<<dim3(32,64),256,2*ST_SZ>>>(ker_b,64);                             // 8
  conv1d_small<64,3,false><<<dim3(16,4,16),256>>>(pr,bias_w,bias_b,pkb,256);   // 9
  convt_pre_k<<<dim3(64,8,16),256>>>(x,ct_w,ct_b,pxa);                         // 10
  const int dils[4]={1,3,9,27};
  const float* srcs[4]={pxa,pxb,pxa,pxb};
  float* dsts[4]={pxb,pxa,pxb,xx};
  for(int i=0;i<4;i++)
    lvc_fused<<<dim3(512,16),256>>>(srcs[i],dsts[i],
        cb_ws+(size_t)i*3072,cb_bs+(size_t)i*32,pkb,i,dils[i]);
}

// round 10
// speedup vs baseline: 1.3006x; 1.1468x over previous
#include <cuda_runtime.h>
#include <cuda_fp16.h>
#include <cstdint>

// ---------------- static device scratch ----------------
__device__ float g_h[16*64*512];
__device__ float g_r[16*64*512];
__device__ float g_kbias[16*256*512];
__device__ float g_kern[201326592];        // 8192 x 24576
__device__ float g_cb[16*32*4096];
__device__ __half g_a16[8192*192];         // A = fp16(im2col(h))
__device__ __half g_b16[24576*384];        // B' = [Bh|Bl] fp16

__device__ __forceinline__ float lrelu(float v){ return v>=0.f ? v : 0.2f*v; }

__device__ __forceinline__ uint32_t smem_u32(const void* p){
  uint32_t a;
  asm("{ .reg .u64 t; cvta.to.shared.u64 t, %1; cvt.u32.u64 %0, t; }":"=r"(a):"l"(p));
  return a;
}
__device__ __forceinline__ void cp16(uint32_t d, const void* s){
  asm volatile("cp.async.cg.shared.global [%0], [%1], 16;"::"r"(d),"l"(s));
}
__device__ __forceinline__ void ldmx4(uint32_t* r, uint32_t a){
  asm volatile("ldmatrix.sync.aligned.m8n8.x4.shared.b16 {%0,%1,%2,%3},[%4];"
    :"=r"(r[0]),"=r"(r[1]),"=r"(r[2]),"=r"(r[3]):"r"(a));
}
__device__ __forceinline__ void mma16816(float* c, const uint32_t* a, uint32_t b0, uint32_t b1){
  asm volatile("mma.sync.aligned.m16n8k16.row.col.f32.f16.f16.f32 "
    "{%0,%1,%2,%3},{%4,%5,%6,%7},{%8,%9},{%0,%1,%2,%3};"
    :"+f"(c[0]),"+f"(c[1]),"+f"(c[2]),"+f"(c[3])
    :"r"(a[0]),"r"(a[1]),"r"(a[2]),"r"(a[3]),"r"(b0),"r"(b1));
}

// ---------------- generic small conv1d over L=512 (32-wide tiles) ----------------
template<int CI,int KS,bool RELU>
__global__ void conv1d_small(const float* __restrict__ in,const float* __restrict__ w,
    const float* __restrict__ bias,float* __restrict__ out,int Cout){
  const int PAD=(KS-1)/2, WDT=32+KS-1;
  const int l0=blockIdx.x*32, cg=blockIdx.y, b=blockIdx.z;
  __shared__ float s[CI][WDT];
  for(int idx=threadIdx.x; idx<CI*WDT; idx+=256){
    int ci=idx/WDT, p=idx-ci*WDT, l=l0+p-PAD;
    s[ci][p]=(l>=0&&l<512)?in[(b*CI+ci)*512+l]:0.f;
  }
  __syncthreads();
  const int co=cg*64+(threadIdx.x>>2), ls=(threadIdx.x&3)*8;
  float acc[8]; float bz=bias[co];
#pragma unroll
  for(int j=0;j<8;j++)acc[j]=bz;
  const float* wr=w+(size_t)co*CI*KS;
  for(int ci=0;ci<CI;ci++){
    float xv[8+KS-1];
#pragma unroll
    for(int j=0;j<8+KS-1;j++)xv[j]=s[ci][ls+j];
#pragma unroll
    for(int k=0;k<KS;k++){
      float wv=__ldg(&wr[ci*KS+k]);
#pragma unroll
      for(int j=0;j<8;j++)acc[j]=fmaf(wv,xv[j+k],acc[j]);
    }
  }
  float* orow=out+((size_t)b*Cout+co)*512+l0+ls;
#pragma unroll
  for(int j=0;j<8;j++){
    float v=acc[j];
    if(RELU)v=lrelu(v);
    orow[j]=v;
  }
}

// ---------------- all 3 residual blocks fused (halo-6 L-tiles) ----------------
// out = trunk after 3x [h += lrelu(conv2(zeropad(lrelu(conv1(h)))))]
// Columns: position p (0..75) stored at index p+1; p <-> global l = l0+p-6.
// After conv stage st (1..6), outputs valid only in band p in [st, 75-st]; outputs at
// global positions outside [0,512) are zeroed (true zero-pad semantics).
__global__ void res3_fused(const float* __restrict__ in,const float* __restrict__ ws,
    const float* __restrict__ bs,float* __restrict__ out){
  const int l0=blockIdx.x*64, b=blockIdx.y, tid=threadIdx.x;
  __shared__ float xb[64][78];
  __shared__ float rb[64][78];
  for(int idx=tid; idx<64*78; idx+=256){
    int ci=idx/78, p1=idx-ci*78;
    int l=l0+p1-7;             // p = p1-1
    float v=0.f;
    if(p1>=1&&p1<=76&&l>=0&&l<512) v=in[(b*64+ci)*512+l];
    xb[ci][p1]=v; rb[ci][p1]=0.f;
  }
  __syncthreads();
  const int co=tid>>2, q=tid&3, p0=q*19;   // positions p0..p0+18
  for(int j=0;j<3;j++){
    // ---- conv1: rb = masked lrelu(conv(xb)) ----
    {
      const int st=2*j+1;
      const float* wr=ws+(size_t)(j*2)*12288+co*192;
      float bz=bs[(j*2)*64+co];
      float acc[19];
#pragma unroll
      for(int t=0;t<19;t++)acc[t]=bz;
      for(int ci=0;ci<64;ci++){
        float w0=__ldg(&wr[ci*3]),w1=__ldg(&wr[ci*3+1]),w2=__ldg(&wr[ci*3+2]);
        const float* xr=&xb[ci][p0];     // xr[t] = pos p0+t-1
#pragma unroll
        for(int t=0;t<19;t++) acc[t]+=w0*xr[t]+w1*xr[t+1]+w2*xr[t+2];
      }
#pragma unroll
      for(int t=0;t<19;t++){
        int p=p0+t, gl=l0+p-6;
        rb[co][p+1]=(p>=st&&p<=75-st&&gl>=0&&gl<512)?lrelu(acc[t]):0.f;
      }
    }
    __syncthreads();
    // ---- conv2 + residual: xb += masked lrelu(conv(rb)) ----
    {
      const int st=2*j+2;
      const float* wr=ws+(size_t)(j*2+1)*12288+co*192;
      float bz=bs[(j*2+1)*64+co];
      float acc[19];
#pragma unroll
      for(int t=0;t<19;t++)acc[t]=bz;
      for(int ci=0;ci<64;ci++){
        float w0=__ldg(&wr[ci*3]),w1=__ldg(&wr[ci*3+1]),w2=__ldg(&wr[ci*3+2]);
        const float* xr=&rb[ci][p0];
#pragma unroll
        for(int t=0;t<19;t++) acc[t]+=w0*xr[t]+w1*xr[t+1]+w2*xr[t+2];
      }
      __syncthreads();   // all reads of rb done before anyone rewrites next iter; xb write is own-row
#pragma unroll
      for(int t=0;t<19;t++){
        int p=p0+t, gl=l0+p-6;
        if(p>=st&&p<=75-st&&gl>=0&&gl<512) xb[co][p+1]+=lrelu(acc[t]);
      }
    }
    __syncthreads();
  }
  // write out band p in [6,69] -> l0..l0+63
  for(int idx=tid; idx<64*64; idx+=256){
    int ci=idx>>6, i=idx&63;
    out[(b*64+ci)*512+l0+i]=xb[ci][i+7];
  }
}

// ---------------- combined A + B' build (one launch) ----------------
__global__ void build_ab_k(const float* __restrict__ kw){
  if(blockIdx.x<6144){
    int idx=blockIdx.x*256+threadIdx.x;         // 8192*192
    int m=idx/192, kk=idx-m*192;
    int b=m>>9, l=m&511, hid=kk/3, t=kk-hid*3;
    int lp=l+t-1;
    float v=(lp>=0&&lp<512)?g_r[(b*64+hid)*512+lp]:0.f;
    g_a16[idx]=__float2half_rn(v);
  }else{
    int idx=(blockIdx.x-6144)*256+threadIdx.x;  // 24576*384
    int n=idx/384, kp=idx-n*384;
    int part=(kp>=192), kk=kp-(part?192:0);
    float v=kw[(size_t)n*192+kk];
    __half hi=__float2half_rn(v);
    g_b16[idx]=part?__float2half_rn(v-__half2float(hi)):hi;
  }
}

// ---------------- mma.sync GEMM, fp16 2-pass: Ah*Bh + Ah*Bl (R7-proven) -----------
#define ST_SZ 49152
__global__ void __launch_bounds__(256,1) gemm_mma(const float* __restrict__ kerb){
  extern __shared__ __align__(128) char smem[];
  const uint32_t sb=smem_u32(smem);
  const int tid=threadIdx.x, lane=tid&31, wid=tid>>5;
  const int wm=wid&1, wn=wid>>1;
  const int m0=blockIdx.y*128, n0=blockIdx.x*256;

  float acc[4][8][4];
#pragma unroll
  for(int i=0;i<4;i++)
#pragma unroll
    for(int j=0;j<8;j++)
#pragma unroll
      for(int k=0;k<4;k++)acc[i][j][k]=0.f;

  auto load_stage=[&](int kc,int st){
    uint32_t abase=sb+st*ST_SZ, bbase=abase+16384;
    const int acol=(kc%3)*64;
#pragma unroll
    for(int i=0;i<4;i++){
      int q=tid+i*256, row=q>>3, c=q&7;
      cp16(abase+row*128+(((c^(row&7)))<<4),
           g_a16+(size_t)(m0+row)*192+acol+c*8);
    }
#pragma unroll
    for(int i=0;i<8;i++){
      int q=tid+i*256, row=q>>3, c=q&7;
      cp16(bbase+row*128+(((c^(row&7)))<<4),
           g_b16+(size_t)(n0+row)*384+kc*64+c*8);
    }
    asm volatile("cp.async.commit_group;");
  };

  load_stage(0,0);
  const int l7=lane&7;
  const int rAoff=l7+((lane>>3)&1)*8, cselA=lane>>4;
  const int rBoff=l7+((lane>>4)&1)*8, cselB=(lane>>3)&1;

  for(int kc=0;kc<6;kc++){
    if(kc<5) load_stage(kc+1,(kc+1)&1);
    if(kc<5) asm volatile("cp.async.wait_group 1;");
    else     asm volatile("cp.async.wait_group 0;");
    __syncthreads();
    uint32_t abase=sb+(kc&1)*ST_SZ, bbase=abase+16384;
#pragma unroll
    for(int ks=0;ks<4;ks++){
      const int c0=ks*2;
      uint32_t ar[4][4], br[4][4];
#pragma unroll
      for(int mi=0;mi<4;mi++){
        int row=wm*64+mi*16+rAoff;
        int cc=c0+cselA;
        ldmx4(ar[mi], abase+row*128+((cc^(row&7))<<4));
      }
#pragma unroll
      for(int np=0;np<4;np++){
        int row=wn*64+np*16+rBoff;
        int cc=c0+cselB;
        ldmx4(br[np], bbase+row*128+((cc^(row&7))<<4));
      }
#pragma unroll
      for(int mi=0;mi<4;mi++)
#pragma unroll
        for(int ni=0;ni<8;ni++)
          mma16816(acc[mi][ni], ar[mi], br[ni>>1][(ni&1)*2], br[ni>>1][(ni&1)*2+1]);
    }
    __syncthreads();
  }

  const int g=lane>>2, t2=(lane&3)*2;
#pragma unroll
  for(int mi=0;mi<4;mi++){
    const int r0=m0+wm*64+mi*16+g;
    float* row0=g_kern+(size_t)r0*24576;
    float* row1=row0+(size_t)8*24576;
#pragma unroll
    for(int ni=0;ni<8;ni++){
      int col=n0+wn*64+ni*8+t2;
      float2 bb=*(const float2*)(kerb+col);
      float2 v0,v1;
      v0.x=acc[mi][ni][0]+bb.x; v0.y=acc[mi][ni][1]+bb.y;
      v1.x=acc[mi][ni][2]+bb.x; v1.y=acc[mi][ni][3]+bb.y;
      *(float2*)(row0+col)=v0;
      *(float2*)(row1+col)=v1;
    }
  }
}

// ---------------- convt_pre: lrelu(x) -> ConvTranspose1d(k=16, s=8, p=4) --------
__global__ void convt_pre_k(const float* __restrict__ x,const float* __restrict__ ctw,
    const float* __restrict__ ctb,float* __restrict__ xx){
  const int b=blockIdx.z, cg=blockIdx.y, t0=blockIdx.x*64, tid=threadIdx.x;
  __shared__ float swt[2048];
  __shared__ float sx[32][12];
  for(int idx=tid;idx<2048;idx+=256){
    int co_l=idx>>9, ci=(idx>>4)&31, kk=idx&15;
    swt[idx]=ctw[(ci*32+cg*4+co_l)*16+kk];
  }
  const int sbase=(t0>>3)-2;
  for(int idx=tid;idx<384;idx+=256){
    int ci=idx/12, j=idx-ci*12, sp=sbase+j;
    sx[ci][j]=(sp>=0&&sp<512)?lrelu(x[(b*32+ci)*512+sp]):0.f;
  }
  __syncthreads();
  const int co_l=tid>>6, t=t0+(tid&63), co=cg*4+co_l;
  const int k0=(8+(11-t)%8)&7;
  const int j=((t+k0-11)>>3)-sbase;
  float acc=ctb[co];
  const float* wl=&swt[co_l*512];
#pragma unroll 8
  for(int ci=0;ci<32;ci++)
    acc+=sx[ci][j]*wl[ci*16+15-k0]+sx[ci][j+1]*wl[ci*16+7-k0];
  xx[(b*32+co)*4096+t]=acc;
}

// ---------------- dilated conv block ----------------
__global__ void conv_block_k(const float* __restrict__ xx,const float* __restrict__ w,
    const float* __restrict__ bias,int dil){
  const int b=blockIdx.z, t0=blockIdx.x*128, tid=threadIdx.x;
  __shared__ float sx[32*182];
  const int W=128+2*dil;
  for(int idx=tid;idx<32*W;idx+=256){
    int ci=idx/W, p=idx-ci*W, t=t0+p-dil;
    sx[ci*182+p]=(t>=0&&t<4096)?lrelu(xx[(b*32+ci)*4096+t]):0.f;
  }
  __syncthreads();
  const int co=tid>>3, lt=(tid&7)*16;
  float acc[16]; float bz=bias[co];
#pragma unroll
  for(int j=0;j<16;j++)acc[j]=bz;
  for(int ci=0;ci<32;ci++){
    float w0=__ldg(&w[(co*32+ci)*3]);
    float w1=__ldg(&w[(co*32+ci)*3+1]);
    float w2=__ldg(&w[(co*32+ci)*3+2]);
    const float* sr=&sx[ci*182+lt];
#pragma unroll
    for(int j=0;j<16;j++)
      acc[j]+=w0*sr[j]+w1*sr[j+dil]+w2*sr[j+2*dil];
  }
  float* orow=&g_cb[(b*32+co)*4096+t0+lt];
#pragma unroll
  for(int j=0;j<16;j++)orow[j]=lrelu(acc[j]);
}

// ---------------- LVC einsum + gated residual update ----------------
__global__ void einsum_gate_k(const float* __restrict__ kbias,float* __restrict__ xx,int layer){
  const int l=blockIdx.x, b=blockIdx.y, tid=threadIdx.x;
  __shared__ __align__(16) float sk[6144];
  __shared__ float sx[32][10];
  __shared__ float so[64][8];
  const float4* kp=(const float4*)(g_kern+((size_t)(b*512+l))*24576+layer*6144);
#pragma unroll
  for(int i=0;i<6;i++) ((float4*)sk)[tid+i*256]=kp[tid+i*256];
  for(int i=tid;i<320;i+=256){
    int ci=i/10, j=i-ci*10, t=l*8+j-1;
    sx[ci][j]=(t>=0&&t<4096)?g_cb[(b*32+ci)*4096+t]:0.f;
  }
  __syncthreads();
  const int o=tid>>2, h2=(tid&3)*2;
  float a0=0.f,a1=0.f;
#pragma unroll 4
  for(int ci=0;ci<32;ci++){
    const float* kb=&sk[ci*192+o*3];
    const float* xr=&sx[ci][h2];
    a0+=xr[0]*kb[0]+xr[1]*kb[1]+xr[2]*kb[2];
    a1+=xr[1]*kb[0]+xr[2]*kb[1]+xr[3]*kb[2];
  }
  const float bb=kbias[((b*4+layer)*64+o)*512+l];
  so[o][h2]=a0+bb; so[o][h2+1]=a1+bb;
  __syncthreads();
  const int co=tid>>3, h=tid&7;
  float g=1.f/(1.f+__expf(-so[co][h]));
  float th=tanhf(so[co+32][h]);
  xx[(b*32+co)*4096+l*8+h]+=g*th;
}

extern "C" void kernel_launch(void* const* d_in,const int* in_sizes,int n_in,
                              void* d_out,int out_size){
  const float* x     =(const float*)d_in[0];
  const float* c     =(const float*)d_in[1];
  const float* in_w  =(const float*)d_in[2];
  const float* in_b  =(const float*)d_in[3];
  const float* res_ws=(const float*)d_in[4];
  const float* res_bs=(const float*)d_in[5];
  const float* ker_w =(const float*)d_in[6];
  const float* ker_b =(const float*)d_in[7];
  const float* bias_w=(const float*)d_in[8];
  const float* bias_b=(const float*)d_in[9];
  const float* ct_w  =(const float*)d_in[10];
  const float* ct_b  =(const float*)d_in[11];
  const float* cb_ws =(const float*)d_in[12];
  const float* cb_bs =(const float*)d_in[13];
  float* xx=(float*)d_out;
  float *ph,*pr,*pkb;
  cudaGetSymbolAddress((void**)&ph, g_h);
  cudaGetSymbolAddress((void**)&pr, g_r);
  cudaGetSymbolAddress((void**)&pkb,g_kbias);

  cudaFuncSetAttribute(gemm_mma, cudaFuncAttributeMaxDynamicSharedMemorySize, 2*ST_SZ);

  conv1d_small<100,5,true><<<dim3(16,1,16),256>>>(c,in_w,in_b,ph,64);   // 1
  res3_fused<<<dim3(8,16),256>>>(ph,res_ws,res_bs,pr);                  // 2
  build_ab_k<<<43008,256>>>(ker_w);                                     // 3
  gemm_mma<<<dim3(96,64),256,2*ST_SZ>>>(ker_b);                         // 4 <-- profiled
  conv1d_small<64,3,false><<<dim3(16,4,16),256>>>(pr,bias_w,bias_b,pkb,256); // 5
  convt_pre_k<<<dim3(64,8,16),256>>>(x,ct_w,ct_b,xx);                   // 6
  const int dils[4]={1,3,9,27};
  for(int i=0;i<4;i++){
    conv_block_k<<<dim3(32,1,16),256>>>(xx,cb_ws+(size_t)i*3072,cb_bs+(size_t)i*32,dils[i]);
    einsum_gate_k<<<dim3(512,16),256>>>(pkb,xx,i);
  }
}

// round 11
// speedup vs baseline: 1.3421x; 1.0319x over previous
#include <cuda_runtime.h>
#include <cuda_fp16.h>
#include <cstdint>

// ---------------- static device scratch ----------------
__device__ float g_h[16*64*512];
__device__ float g_r[16*64*512];
__device__ float g_kbias[16*256*512];
__device__ float g_kern[201326592];        // 8192 x 24576
__device__ float g_cb[16*32*4096];
__device__ __half g_a16[8192*192];         // A = fp16(im2col(h))
__device__ __half g_b16[24576*384];        // B' = [Bh|Bl] fp16

__device__ __forceinline__ float lrelu(float v){ return v>=0.f ? v : 0.2f*v; }

__device__ __forceinline__ uint32_t smem_u32(const void* p){
  uint32_t a;
  asm("{ .reg .u64 t; cvta.to.shared.u64 t, %1; cvt.u32.u64 %0, t; }":"=r"(a):"l"(p));
  return a;
}
__device__ __forceinline__ void cp16(uint32_t d, const void* s){
  asm volatile("cp.async.cg.shared.global [%0], [%1], 16;"::"r"(d),"l"(s));
}
__device__ __forceinline__ void ldmx4(uint32_t* r, uint32_t a){
  asm volatile("ldmatrix.sync.aligned.m8n8.x4.shared.b16 {%0,%1,%2,%3},[%4];"
    :"=r"(r[0]),"=r"(r[1]),"=r"(r[2]),"=r"(r[3]):"r"(a));
}
__device__ __forceinline__ void mma16816(float* c, const uint32_t* a, uint32_t b0, uint32_t b1){
  asm volatile("mma.sync.aligned.m16n8k16.row.col.f32.f16.f16.f32 "
    "{%0,%1,%2,%3},{%4,%5,%6,%7},{%8,%9},{%0,%1,%2,%3};"
    :"+f"(c[0]),"+f"(c[1]),"+f"(c[2]),"+f"(c[3])
    :"r"(a[0]),"r"(a[1]),"r"(a[2]),"r"(a[3]),"r"(b0),"r"(b1));
}

// ---------------- generic small conv1d over L=512 (32-wide tiles) ----------------
template<int CI,int KS,bool RELU>
__global__ void conv1d_small(const float* __restrict__ in,const float* __restrict__ w,
    const float* __restrict__ bias,float* __restrict__ out,int Cout){
  const int PAD=(KS-1)/2, WDT=32+KS-1;
  const int l0=blockIdx.x*32, cg=blockIdx.y, b=blockIdx.z;
  __shared__ float s[CI][WDT];
  for(int idx=threadIdx.x; idx<CI*WDT; idx+=256){
    int ci=idx/WDT, p=idx-ci*WDT, l=l0+p-PAD;
    s[ci][p]=(l>=0&&l<512)?in[(b*CI+ci)*512+l]:0.f;
  }
  __syncthreads();
  const int co=cg*64+(threadIdx.x>>2), ls=(threadIdx.x&3)*8;
  float acc[8]; float bz=bias[co];
#pragma unroll
  for(int j=0;j<8;j++)acc[j]=bz;
  const float* wr=w+(size_t)co*CI*KS;
  for(int ci=0;ci<CI;ci++){
    float xv[8+KS-1];
#pragma unroll
    for(int j=0;j<8+KS-1;j++)xv[j]=s[ci][ls+j];
#pragma unroll
    for(int k=0;k<KS;k++){
      float wv=__ldg(&wr[ci*KS+k]);
#pragma unroll
      for(int j=0;j<8;j++)acc[j]=fmaf(wv,xv[j+k],acc[j]);
    }
  }
  float* orow=out+((size_t)b*Cout+co)*512+l0+ls;
#pragma unroll
  for(int j=0;j<8;j++){
    float v=acc[j];
    if(RELU)v=lrelu(v);
    orow[j]=v;
  }
}

// ---------------- all 3 residual blocks fused (halo-6 L-tiles) ----------------
__global__ void res3_fused(const float* __restrict__ in,const float* __restrict__ ws,
    const float* __restrict__ bs,float* __restrict__ out){
  const int l0=blockIdx.x*64, b=blockIdx.y, tid=threadIdx.x;
  __shared__ float xb[64][78];
  __shared__ float rb[64][78];
  for(int idx=tid; idx<64*78; idx+=256){
    int ci=idx/78, p1=idx-ci*78;
    int l=l0+p1-7;
    float v=0.f;
    if(p1>=1&&p1<=76&&l>=0&&l<512) v=in[(b*64+ci)*512+l];
    xb[ci][p1]=v; rb[ci][p1]=0.f;
  }
  __syncthreads();
  const int co=tid>>2, q=tid&3, p0=q*19;
  for(int j=0;j<3;j++){
    {
      const int st=2*j+1;
      const float* wr=ws+(size_t)(j*2)*12288+co*192;
      float bz=bs[(j*2)*64+co];
      float acc[19];
#pragma unroll
      for(int t=0;t<19;t++)acc[t]=bz;
      for(int ci=0;ci<64;ci++){
        float w0=__ldg(&wr[ci*3]),w1=__ldg(&wr[ci*3+1]),w2=__ldg(&wr[ci*3+2]);
        const float* xr=&xb[ci][p0];
#pragma unroll
        for(int t=0;t<19;t++) acc[t]+=w0*xr[t]+w1*xr[t+1]+w2*xr[t+2];
      }
#pragma unroll
      for(int t=0;t<19;t++){
        int p=p0+t, gl=l0+p-6;
        rb[co][p+1]=(p>=st&&p<=75-st&&gl>=0&&gl<512)?lrelu(acc[t]):0.f;
      }
    }
    __syncthreads();
    {
      const int st=2*j+2;
      const float* wr=ws+(size_t)(j*2+1)*12288+co*192;
      float bz=bs[(j*2+1)*64+co];
      float acc[19];
#pragma unroll
      for(int t=0;t<19;t++)acc[t]=bz;
      for(int ci=0;ci<64;ci++){
        float w0=__ldg(&wr[ci*3]),w1=__ldg(&wr[ci*3+1]),w2=__ldg(&wr[ci*3+2]);
        const float* xr=&rb[ci][p0];
#pragma unroll
        for(int t=0;t<19;t++) acc[t]+=w0*xr[t]+w1*xr[t+1]+w2*xr[t+2];
      }
      __syncthreads();
#pragma unroll
      for(int t=0;t<19;t++){
        int p=p0+t, gl=l0+p-6;
        if(p>=st&&p<=75-st&&gl>=0&&gl<512) xb[co][p+1]+=lrelu(acc[t]);
      }
    }
    __syncthreads();
  }
  for(int idx=tid; idx<64*64; idx+=256){
    int ci=idx>>6, i=idx&63;
    out[(b*64+ci)*512+l0+i]=xb[ci][i+7];
  }
}

// ---------------- combined A + B' build (one launch) ----------------
__global__ void build_ab_k(const float* __restrict__ kw){
  if(blockIdx.x<6144){
    int idx=blockIdx.x*256+threadIdx.x;         // 8192*192
    int m=idx/192, kk=idx-m*192;
    int b=m>>9, l=m&511, hid=kk/3, t=kk-hid*3;
    int lp=l+t-1;
    float v=(lp>=0&&lp<512)?g_r[(b*64+hid)*512+lp]:0.f;
    g_a16[idx]=__float2half_rn(v);
  }else{
    int idx=(blockIdx.x-6144)*256+threadIdx.x;  // 24576*384
    int n=idx/384, kp=idx-n*384;
    int part=(kp>=192), kk=kp-(part?192:0);
    float v=kw[(size_t)n*192+kk];
    __half hi=__float2half_rn(v);
    g_b16[idx]=part?__float2half_rn(v-__half2float(hi)):hi;
  }
}

// ---------------- mma.sync GEMM, fp16 2-pass, 512 threads / 16 warps --------------
// CTA 128m x 256n; warp grid 2m x 8n; warp tile 64m x 32n (acc 64 regs/thread).
// Same staging (2 x 48KB), same k order -> bit-identical results to R10.
#define ST_SZ 49152
__global__ void __launch_bounds__(512,1) gemm_mma(const float* __restrict__ kerb){
  extern __shared__ __align__(128) char smem[];
  const uint32_t sb=smem_u32(smem);
  const int tid=threadIdx.x, lane=tid&31, wid=tid>>5;
  const int wm=wid&1, wn=wid>>1;          // wn in 0..7
  const int m0=blockIdx.y*128, n0=blockIdx.x*256;

  float acc[4][4][4];
#pragma unroll
  for(int i=0;i<4;i++)
#pragma unroll
    for(int j=0;j<4;j++)
#pragma unroll
      for(int k=0;k<4;k++)acc[i][j][k]=0.f;

  auto load_stage=[&](int kc,int st){
    uint32_t abase=sb+st*ST_SZ, bbase=abase+16384;
    const int acol=(kc%3)*64;
#pragma unroll
    for(int i=0;i<2;i++){
      int q=tid+i*512, row=q>>3, c=q&7;
      cp16(abase+row*128+(((c^(row&7)))<<4),
           g_a16+(size_t)(m0+row)*192+acol+c*8);
    }
#pragma unroll
    for(int i=0;i<4;i++){
      int q=tid+i*512, row=q>>3, c=q&7;
      cp16(bbase+row*128+(((c^(row&7)))<<4),
           g_b16+(size_t)(n0+row)*384+kc*64+c*8);
    }
    asm volatile("cp.async.commit_group;");
  };

  load_stage(0,0);
  const int l7=lane&7;
  const int rAoff=l7+((lane>>3)&1)*8, cselA=lane>>4;
  const int rBoff=l7+((lane>>4)&1)*8, cselB=(lane>>3)&1;

  for(int kc=0;kc<6;kc++){
    if(kc<5) load_stage(kc+1,(kc+1)&1);
    if(kc<5) asm volatile("cp.async.wait_group 1;");
    else     asm volatile("cp.async.wait_group 0;");
    __syncthreads();
    uint32_t abase=sb+(kc&1)*ST_SZ, bbase=abase+16384;
#pragma unroll
    for(int ks=0;ks<4;ks++){
      const int c0=ks*2;
      uint32_t ar[4][4], br[2][4];
#pragma unroll
      for(int mi=0;mi<4;mi++){
        int row=wm*64+mi*16+rAoff;
        int cc=c0+cselA;
        ldmx4(ar[mi], abase+row*128+((cc^(row&7))<<4));
      }
#pragma unroll
      for(int np=0;np<2;np++){
        int row=wn*32+np*16+rBoff;
        int cc=c0+cselB;
        ldmx4(br[np], bbase+row*128+((cc^(row&7))<<4));
      }
#pragma unroll
      for(int mi=0;mi<4;mi++)
#pragma unroll
        for(int ni=0;ni<4;ni++)
          mma16816(acc[mi][ni], ar[mi], br[ni>>1][(ni&1)*2], br[ni>>1][(ni&1)*2+1]);
    }
    __syncthreads();
  }

  const int g=lane>>2, t2=(lane&3)*2;
#pragma unroll
  for(int mi=0;mi<4;mi++){
    const int r0=m0+wm*64+mi*16+g;
    float* row0=g_kern+(size_t)r0*24576;
    float* row1=row0+(size_t)8*24576;
#pragma unroll
    for(int ni=0;ni<4;ni++){
      int col=n0+wn*32+ni*8+t2;
      float2 bb=*(const float2*)(kerb+col);
      float2 v0,v1;
      v0.x=acc[mi][ni][0]+bb.x; v0.y=acc[mi][ni][1]+bb.y;
      v1.x=acc[mi][ni][2]+bb.x; v1.y=acc[mi][ni][3]+bb.y;
      *(float2*)(row0+col)=v0;
      *(float2*)(row1+col)=v1;
    }
  }
}

// ---------------- convt_pre: lrelu(x) -> ConvTranspose1d(k=16, s=8, p=4) --------
__global__ void convt_pre_k(const float* __restrict__ x,const float* __restrict__ ctw,
    const float* __restrict__ ctb,float* __restrict__ xx){
  const int b=blockIdx.z, cg=blockIdx.y, t0=blockIdx.x*64, tid=threadIdx.x;
  __shared__ float swt[2048];
  __shared__ float sx[32][12];
  for(int idx=tid;idx<2048;idx+=256){
    int co_l=idx>>9, ci=(idx>>4)&31, kk=idx&15;
    swt[idx]=ctw[(ci*32+cg*4+co_l)*16+kk];
  }
  const int sbase=(t0>>3)-2;
  for(int idx=tid;idx<384;idx+=256){
    int ci=idx/12, j=idx-ci*12, sp=sbase+j;
    sx[ci][j]=(sp>=0&&sp<512)?lrelu(x[(b*32+ci)*512+sp]):0.f;
  }
  __syncthreads();
  const int co_l=tid>>6, t=t0+(tid&63), co=cg*4+co_l;
  const int k0=(8+(11-t)%8)&7;
  const int j=((t+k0-11)>>3)-sbase;
  float acc=ctb[co];
  const float* wl=&swt[co_l*512];
#pragma unroll 8
  for(int ci=0;ci<32;ci++)
    acc+=sx[ci][j]*wl[ci*16+15-k0]+sx[ci][j+1]*wl[ci*16+7-k0];
  xx[(b*32+co)*4096+t]=acc;
}

// ---------------- dilated conv block ----------------
__global__ void conv_block_k(const float* __restrict__ xx,const float* __restrict__ w,
    const float* __restrict__ bias,int dil){
  const int b=blockIdx.z, t0=blockIdx.x*128, tid=threadIdx.x;
  __shared__ float sx[32*182];
  const int W=128+2*dil;
  for(int idx=tid;idx<32*W;idx+=256){
    int ci=idx/W, p=idx-ci*W, t=t0+p-dil;
    sx[ci*182+p]=(t>=0&&t<4096)?lrelu(xx[(b*32+ci)*4096+t]):0.f;
  }
  __syncthreads();
  const int co=tid>>3, lt=(tid&7)*16;
  float acc[16]; float bz=bias[co];
#pragma unroll
  for(int j=0;j<16;j++)acc[j]=bz;
  for(int ci=0;ci<32;ci++){
    float w0=__ldg(&w[(co*32+ci)*3]);
    float w1=__ldg(&w[(co*32+ci)*3+1]);
    float w2=__ldg(&w[(co*32+ci)*3+2]);
    const float* sr=&sx[ci*182+lt];
#pragma unroll
    for(int j=0;j<16;j++)
      acc[j]+=w0*sr[j]+w1*sr[j+dil]+w2*sr[j+2*dil];
  }
  float* orow=&g_cb[(b*32+co)*4096+t0+lt];
#pragma unroll
  for(int j=0;j<16;j++)orow[j]=lrelu(acc[j]);
}

// ---------------- LVC einsum + gated residual update ----------------
__global__ void einsum_gate_k(const float* __restrict__ kbias,float* __restrict__ xx,int layer){
  const int l=blockIdx.x, b=blockIdx.y, tid=threadIdx.x;
  __shared__ __align__(16) float sk[6144];
  __shared__ float sx[32][10];
  __shared__ float so[64][8];
  const float4* kp=(const float4*)(g_kern+((size_t)(b*512+l))*24576+layer*6144);
#pragma unroll
  for(int i=0;i<6;i++) ((float4*)sk)[tid+i*256]=__ldcs(&kp[tid+i*256]);
  for(int i=tid;i<320;i+=256){
    int ci=i/10, j=i-ci*10, t=l*8+j-1;
    sx[ci][j]=(t>=0&&t<4096)?g_cb[(b*32+ci)*4096+t]:0.f;
  }
  __syncthreads();
  const int o=tid>>2, h2=(tid&3)*2;
  float a0=0.f,a1=0.f;
#pragma unroll 4
  for(int ci=0;ci<32;ci++){
    const float* kb=&sk[ci*192+o*3];
    const float* xr=&sx[ci][h2];
    a0+=xr[0]*kb[0]+xr[1]*kb[1]+xr[2]*kb[2];
    a1+=xr[1]*kb[0]+xr[2]*kb[1]+xr[3]*kb[2];
  }
  const float bb=kbias[((b*4+layer)*64+o)*512+l];
  so[o][h2]=a0+bb; so[o][h2+1]=a1+bb;
  __syncthreads();
  const int co=tid>>3, h=tid&7;
  float g=1.f/(1.f+__expf(-so[co][h]));
  float th=tanhf(so[co+32][h]);
  xx[(b*32+co)*4096+l*8+h]+=g*th;
}

extern "C" void kernel_launch(void* const* d_in,const int* in_sizes,int n_in,
                              void* d_out,int out_size){
  const float* x     =(const float*)d_in[0];
  const float* c     =(const float*)d_in[1];
  const float* in_w  =(const float*)d_in[2];
  const float* in_b  =(const float*)d_in[3];
  const float* res_ws=(const float*)d_in[4];
  const float* res_bs=(const float*)d_in[5];
  const float* ker_w =(const float*)d_in[6];
  const float* ker_b =(const float*)d_in[7];
  const float* bias_w=(const float*)d_in[8];
  const float* bias_b=(const float*)d_in[9];
  const float* ct_w  =(const float*)d_in[10];
  const float* ct_b  =(const float*)d_in[11];
  const float* cb_ws =(const float*)d_in[12];
  const float* cb_bs =(const float*)d_in[13];
  float* xx=(float*)d_out;
  float *ph,*pr,*pkb;
  cudaGetSymbolAddress((void**)&ph, g_h);
  cudaGetSymbolAddress((void**)&pr, g_r);
  cudaGetSymbolAddress((void**)&pkb,g_kbias);

  cudaFuncSetAttribute(gemm_mma, cudaFuncAttributeMaxDynamicSharedMemorySize, 2*ST_SZ);

  conv1d_small<100,5,true><<<dim3(16,1,16),256>>>(c,in_w,in_b,ph,64);   // 1
  res3_fused<<<dim3(8,16),256>>>(ph,res_ws,res_bs,pr);                  // 2
  build_ab_k<<<43008,256>>>(ker_w);                                     // 3
  gemm_mma<<<dim3(96,64),512,2*ST_SZ>>>(ker_b);                         // 4 <-- profiled
  conv1d_small<64,3,false><<<dim3(16,4,16),256>>>(pr,bias_w,bias_b,pkb,256); // 5
  convt_pre_k<<<dim3(64,8,16),256>>>(x,ct_w,ct_b,xx);                   // 6
  const int dils[4]={1,3,9,27};
  for(int i=0;i<4;i++){
    conv_block_k<<<dim3(32,1,16),256>>>(xx,cb_ws+(size_t)i*3072,cb_bs+(size_t)i*32,dils[i]);
    einsum_gate_k<<<dim3(512,16),256>>>(pkb,xx,i);
  }
}